// round 17
// baseline (speedup 1.0000x reference)
#include <cuda_runtime.h>
#include <cuda_fp16.h>
#include <cstdint>

// Problem constants (fixed by the reference: LENGTHS[i] = 1024 + 128*i, B=16)
#define T_TOK   31744
#define PREV    768
#define DIM     256
#define NDOCS   16
#define MAXLEN  2944

// GEMM tiling: CTA 64x128 (split-N), 8 warps as 2(M) x 4(N), warp tile 32x32
#define BM 64
#define BNH 128
#define BK 32
#define NTHREADS 256
#define KTILES (PREV / BK)             // 24

// Fragment-major smem stages (u32 elements), fp16 data
#define A_STAGE 1024                   // 64x32 fp16 = 4 KB
#define B_STAGE 2048                   // 32x128 fp16 = 8 KB
#define SMEM_BYTES ((2 * A_STAGE + 2 * B_STAGE) * 4)   // 24576 B

#define GRID_GEMM (2 * (T_TOK / BM))   // 992 (mt = bx>>1, nh = bx&1)
#define PAD_ROWS  (NDOCS * MAXLEN - T_TOK)  // 15360
#define ZBLOCKS   120
#define ROWS_PER_Z (PAD_ROWS / ZBLOCKS)     // 128

// W pre-converted to fp16, fragment-pair-major per (32-k, 128-n) half-tile.
// 48 half-tiles of 2048 u32 each: block = kt*2 + nh.
__device__ uint16_t g_WH[PREV * DIM];

// ---------------- helpers ----------------
__device__ __forceinline__ int doc_offset(int b) { return 1024 * b + 64 * b * (b - 1); }
__device__ __forceinline__ int pad_offset(int b) { return 1920 * b - 64 * b * (b - 1); }

__device__ __forceinline__ int out_row_for_token(int t) {
    int b = 0;
#pragma unroll
    for (int i = 1; i < NDOCS; ++i) if (t >= doc_offset(i)) b = i;
    return b * MAXLEN + (t - doc_offset(b));
}
__device__ __forceinline__ int out_row_for_pad(int p) {
    int b = 0;
#pragma unroll
    for (int i = 1; i < NDOCS; ++i) if (p >= pad_offset(i)) b = i;
    return b * MAXLEN + (1024 + 128 * b) + (p - pad_offset(b));
}

__device__ __forceinline__ uint32_t smem_u32_addr(const void* p) {
    uint32_t a;
    asm("{ .reg .u64 t; cvta.to.shared.u64 t, %1; cvt.u32.u64 %0, t; }" : "=r"(a) : "l"(p));
    return a;
}

__device__ __forceinline__ void mma_f16(float* d, const uint32_t* a, const uint32_t* b) {
    asm volatile(
        "mma.sync.aligned.m16n8k16.row.col.f32.f16.f16.f32 "
        "{%0,%1,%2,%3}, {%4,%5,%6,%7}, {%8,%9}, {%0,%1,%2,%3};"
        : "+f"(d[0]), "+f"(d[1]), "+f"(d[2]), "+f"(d[3])
        : "r"(a[0]), "r"(a[1]), "r"(a[2]), "r"(a[3]), "r"(b[0]), "r"(b[1]));
}

#define CP_ASYNC16(dst_u32, src_ptr) \
    asm volatile("cp.async.cg.shared.global [%0], [%1], 16;" \
                 :: "r"(dst_u32), "l"(src_ptr) : "memory")
#define CP_COMMIT() asm volatile("cp.async.commit_group;" ::: "memory")
#define CP_WAIT0()  asm volatile("cp.async.wait_group 0;" ::: "memory")

__device__ __forceinline__ uint32_t h2u(float x, float y) {
    __half2 h = __float22half2_rn(make_float2(x, y));
    return *reinterpret_cast<uint32_t*>(&h);
}

// ---------------- W convert + permute (gather form, coalesced writes) ----
// B u32 layout within one (32k x 128n) half-tile (2048 u32):
//   u32idx = ((((kk*4+wN)*2+p)*8+gid)*4 + t4)*4 + q,  q = o*2 + reg
//   n_local = wN*32 + (2p+o)*8 + gid
//   k_local = kk*16 + reg*8 + t4*2 + half
__global__ void round_w_kernel(const float* __restrict__ W) {
    int t = blockIdx.x * 256 + threadIdx.x;     // uint4 index, 0..24575
    int blk = t >> 9;                           // 512 uint4 per half-tile
    int kt  = blk >> 1;
    int nh  = blk & 1;
    int tl  = t & 511;
    int t4  = tl & 3;
    int gid = (tl >> 2) & 7;
    int p   = (tl >> 5) & 1;
    int wN  = (tl >> 6) & 3;
    int kk  = (tl >> 8) & 1;
    uint32_t u[4];
#pragma unroll
    for (int q = 0; q < 4; ++q) {
        int o = q >> 1, reg = q & 1;
        int n = nh * BNH + wN * 32 + (2 * p + o) * 8 + gid;
        int k0 = kt * BK + kk * 16 + reg * 8 + t4 * 2;
        u[q] = h2u(W[(size_t)k0 * DIM + n], W[(size_t)(k0 + 1) * DIM + n]);
    }
    reinterpret_cast<uint4*>(g_WH)[t] = make_uint4(u[0], u[1], u[2], u[3]);
}

// A fragment-major u32 index within one 64x32 K-tile (1024 u32), XOR swizzle.
__device__ __forceinline__ int a_frag_u32(int m, int kl) {
    int warpM = m >> 5, mi = (m >> 4) & 1, rb8 = (m >> 3) & 1, gid = m & 7;
    int kk = kl >> 4, k16 = kl & 15;
    int khi = k16 >> 3, t4 = (k16 & 7) >> 1;
    int t4s = (t4 ^ (gid & 3) ^ kk) & 3;
    return ((((kk * 2 + warpM) * 2 + mi) * 8 + gid) * 4 + t4s) * 4 + khi * 2 + rb8;
}

// ---------------- main fused kernel ----------------
__global__ __launch_bounds__(NTHREADS, 3)
void gemm_tc_scatter_kernel(const float* __restrict__ A,
                            const float* __restrict__ bias,
                            float* __restrict__ out) {
    extern __shared__ uint32_t sm[];
    uint32_t* AsBase = sm;                    // [2][A_STAGE]
    uint32_t* BsBase = sm + 2 * A_STAGE;      // [2][B_STAGE]

    const int tid = threadIdx.x;
    const int bx  = blockIdx.x;

    // ---- tail blocks: zero padding rows ----
    if (bx >= GRID_GEMM) {
        const int p0 = (bx - GRID_GEMM) * ROWS_PER_Z;
        for (int i = tid; i < ROWS_PER_Z * (DIM / 4); i += NTHREADS) {
            int row = out_row_for_pad(p0 + (i >> 6));
            reinterpret_cast<float4*>(out + (size_t)row * DIM)[i & 63] =
                make_float4(0.f, 0.f, 0.f, 0.f);
        }
        return;
    }

    const int mt = bx >> 1;
    const int nh = bx & 1;
    const int m0 = mt * BM;

    const int lane   = tid & 31;
    const int warpId = tid >> 5;
    const int warpM  = warpId & 1;      // 0..1 -> 32 rows each
    const int warpN  = warpId >> 1;     // 0..3 -> 32 cols each
    const int nbg    = nh * BNH + warpN * 32;
    const int gid    = lane >> 2;       // 0..7
    const int t4     = lane & 3;        // 0..3

    // A fill coords: rows am0, am0+32 at k floats ak..ak+3
    const int am0 = tid >> 3;                 // 0..31
    const int am1 = am0 + 32;
    const int ak  = (tid & 7) * 4;            // 0,4,...,28
    const float* aP0 = A + (size_t)(m0 + am0) * PREV + ak;
    const float* aP1 = A + (size_t)(m0 + am1) * PREV + ak;

    int sa0[2], sa1[2];
    sa0[0] = a_frag_u32(am0, ak);  sa0[1] = a_frag_u32(am0, ak + 2);
    sa1[0] = a_frag_u32(am1, ak);  sa1[1] = a_frag_u32(am1, ak + 2);

    const uint32_t bsm = smem_u32_addr(BsBase);
    const uint16_t* wsrc = g_WH + (size_t)nh * (2 * B_STAGE);  // + kt*(4*B_STAGE)

    float acc[2][4][4];
#pragma unroll
    for (int mi = 0; mi < 2; ++mi)
#pragma unroll
        for (int ni = 0; ni < 4; ++ni)
#pragma unroll
            for (int j = 0; j < 4; ++j) acc[mi][ni][j] = 0.f;

    // ---- prologue: A0 cvt+sts, B0 cp.async; prefetch A1 ----
    {
        float4 a0 = *reinterpret_cast<const float4*>(aP0);
        float4 a1 = *reinterpret_cast<const float4*>(aP1);
        uint32_t* As = AsBase;
        As[sa0[0]] = h2u(a0.x, a0.y); As[sa0[1]] = h2u(a0.z, a0.w);
        As[sa1[0]] = h2u(a1.x, a1.y); As[sa1[1]] = h2u(a1.z, a1.w);
#pragma unroll
        for (int i = 0; i < 2; ++i) {
            int c = tid + i * NTHREADS;      // 16B chunk 0..511
            CP_ASYNC16(bsm + (uint32_t)c * 16, wsrc + c * 8);
        }
        CP_COMMIT();
    }
    float4 pa0 = *reinterpret_cast<const float4*>(aP0 + BK);
    float4 pa1 = *reinterpret_cast<const float4*>(aP1 + BK);

    for (int kt = 0; kt < KTILES; ++kt) {
        const int cur = kt & 1;
        const int nxt = cur ^ 1;
        const bool more = (kt + 1 < KTILES);

        CP_WAIT0();          // B(kt) resident
        __syncthreads();     // fills visible; stage nxt free of readers

        // commit B(kt+1)
        if (more) {
            const uint16_t* src = wsrc + (size_t)(kt + 1) * (4 * B_STAGE / 2) * 2;
#pragma unroll
            for (int i = 0; i < 2; ++i) {
                int c = tid + i * NTHREADS;
                CP_ASYNC16(bsm + (uint32_t)(nxt * B_STAGE + c * 4) * 4, src + c * 8);
            }
            CP_COMMIT();
        }

        // ---- compute tile kt: 2 k-steps of 16 ----
        const uint32_t* As = AsBase + cur * A_STAGE;
        const uint32_t* Bs = BsBase + cur * B_STAGE;
#pragma unroll
        for (int kk = 0; kk < 2; ++kk) {
            uint32_t af[2][4];
#pragma unroll
            for (int mi = 0; mi < 2; ++mi) {
                int g = ((((kk * 2 + warpM) * 2 + mi) * 8 + gid) * 4 +
                         ((t4 ^ (gid & 3) ^ kk) & 3)) * 4;
                uint4 v = *reinterpret_cast<const uint4*>(As + g);
                af[mi][0] = v.x; af[mi][1] = v.y; af[mi][2] = v.z; af[mi][3] = v.w;
            }
            uint32_t bf[4][2];
#pragma unroll
            for (int p = 0; p < 2; ++p) {
                int g = ((((kk * 4 + warpN) * 2 + p) * 8 + gid) * 4 + t4) * 4;
                uint4 v = *reinterpret_cast<const uint4*>(Bs + g);
                bf[2 * p][0] = v.x; bf[2 * p][1] = v.y;
                bf[2 * p + 1][0] = v.z; bf[2 * p + 1][1] = v.w;
            }
#pragma unroll
            for (int ni = 0; ni < 4; ++ni) {
                mma_f16(acc[0][ni], af[0], bf[ni]);
                mma_f16(acc[1][ni], af[1], bf[ni]);
            }
        }

        // ---- store A(kt+1); prefetch A(kt+2) ----
        if (more) {
            uint32_t* Asn = AsBase + nxt * A_STAGE;
            Asn[sa0[0]] = h2u(pa0.x, pa0.y); Asn[sa0[1]] = h2u(pa0.z, pa0.w);
            Asn[sa1[0]] = h2u(pa1.x, pa1.y); Asn[sa1[1]] = h2u(pa1.z, pa1.w);
            if (kt + 2 < KTILES) {
                const int k0 = (kt + 2) * BK;
                pa0 = *reinterpret_cast<const float4*>(aP0 + k0);
                pa1 = *reinterpret_cast<const float4*>(aP1 + k0);
            }
        }
    }

    // ---- epilogue: bias + ragged scatter ----
    float2 bv[4];
#pragma unroll
    for (int ni = 0; ni < 4; ++ni)
        bv[ni] = *reinterpret_cast<const float2*>(bias + nbg + ni * 8 + 2 * t4);

#pragma unroll
    for (int mi = 0; mi < 2; ++mi) {
        const int r0 = m0 + warpM * 32 + mi * 16 + gid;
        const int o0 = out_row_for_token(r0);
        const int o1 = out_row_for_token(r0 + 8);
        float* p0 = out + (size_t)o0 * DIM + nbg + 2 * t4;
        float* p1 = out + (size_t)o1 * DIM + nbg + 2 * t4;
#pragma unroll
        for (int ni = 0; ni < 4; ++ni) {
            float2 v0, v1;
            v0.x = acc[mi][ni][0] + bv[ni].x;
            v0.y = acc[mi][ni][1] + bv[ni].y;
            v1.x = acc[mi][ni][2] + bv[ni].x;
            v1.y = acc[mi][ni][3] + bv[ni].y;
            *reinterpret_cast<float2*>(p0 + ni * 8) = v0;
            *reinterpret_cast<float2*>(p1 + ni * 8) = v1;
        }
    }
}

extern "C" void kernel_launch(void* const* d_in, const int* in_sizes, int n_in,
                              void* d_out, int out_size) {
    const float* A    = (const float*)d_in[0];  // sent_embs [T_TOK, PREV]
    const float* W    = (const float*)d_in[1];  // [PREV, DIM]
    const float* bias = (const float*)d_in[2];  // [DIM]
    float* out = (float*)d_out;                 // [NDOCS*MAXLEN, DIM]

    cudaFuncSetAttribute(gemm_tc_scatter_kernel,
                         cudaFuncAttributeMaxDynamicSharedMemorySize, SMEM_BYTES);

    round_w_kernel<<<(PREV * DIM / 8) / 256, 256>>>(W);
    gemm_tc_scatter_kernel<<<GRID_GEMM + ZBLOCKS, NTHREADS, SMEM_BYTES>>>(A, bias, out);
}